// round 1
// baseline (speedup 1.0000x reference)
#include <cuda_runtime.h>
#include <cuda_bf16.h>

// Problem: B=4, T=4096, C=384 (n_embd), H=16 (head_size)
// out[b,t,:] = softmax_causal( (x@Wq)(x@Wk)^T / sqrt(H) ) @ (x@Wv)

#define B_   4
#define T_   4096
#define C_   384
#define H_   16
#define BT_  (B_ * T_)            // 16384 rows

// Scratch: q (pre-scaled by 1/4 * log2(e)), k, v  — [B*T, 16] fp32, 1 MB each
__device__ float g_q[BT_ * H_];
__device__ float g_k[BT_ * H_];
__device__ float g_v[BT_ * H_];

__device__ __forceinline__ float ex2(float x) {
    float y;
    asm("ex2.approx.ftz.f32 %0, %1;" : "=f"(y) : "f"(x));
    return y;
}

// ---------------------------------------------------------------------------
// Kernel 1: fused QKV projection.
// Block = 128 threads, each thread owns one row of x (one token).
// x chunk [128 rows x 64 cols] staged in smem (pad 65 to kill bank conflicts),
// W chunks [64 x 16] x3 in smem (broadcast reads).
// q is pre-scaled by (H^-0.5 * log2 e) so attention can use ex2 directly.
// ---------------------------------------------------------------------------
__global__ __launch_bounds__(128, 1)
void proj_kernel(const float* __restrict__ x,
                 const float* __restrict__ Wk,
                 const float* __restrict__ Wq,
                 const float* __restrict__ Wv) {
    __shared__ float sx[128 * 65];
    __shared__ float swk[64 * 16];
    __shared__ float swq[64 * 16];
    __shared__ float swv[64 * 16];

    const int tid = threadIdx.x;
    const long row0 = (long)blockIdx.x * 128;

    float aK[16], aQ[16], aV[16];
#pragma unroll
    for (int h = 0; h < 16; h++) { aK[h] = 0.f; aQ[h] = 0.f; aV[h] = 0.f; }

    const float4* xg = (const float4*)x;   // row stride = 96 float4

    for (int cc = 0; cc < 6; cc++) {       // 6 chunks of 64 over C=384
        // stage x[128][64] (coalesced: 16 consecutive float4 per row)
        for (int i = tid; i < 128 * 16; i += 128) {
            int r  = i >> 4;
            int c4 = i & 15;
            float4 v = xg[(row0 + r) * 96 + cc * 16 + c4];
            float* d = &sx[r * 65 + c4 * 4];
            d[0] = v.x; d[1] = v.y; d[2] = v.z; d[3] = v.w;
        }
        // stage W chunks (contiguous 64*16 floats each)
        for (int i = tid; i < 256; i += 128) {
            ((float4*)swk)[i] = ((const float4*)(Wk + cc * 1024))[i];
            ((float4*)swq)[i] = ((const float4*)(Wq + cc * 1024))[i];
            ((float4*)swv)[i] = ((const float4*)(Wv + cc * 1024))[i];
        }
        __syncthreads();

        const float* xr = &sx[tid * 65];
#pragma unroll 4
        for (int c = 0; c < 64; c++) {
            float xv = xr[c];
            const float* wkc = &swk[c * 16];
            const float* wqc = &swq[c * 16];
            const float* wvc = &swv[c * 16];
#pragma unroll
            for (int h = 0; h < 16; h++) {
                aK[h] = fmaf(xv, wkc[h], aK[h]);
                aQ[h] = fmaf(xv, wqc[h], aQ[h]);
                aV[h] = fmaf(xv, wvc[h], aV[h]);
            }
        }
        __syncthreads();
    }

    const float qscale = 0.25f * 1.4426950408889634f;  // H^-0.5 * log2(e)
    const long row = row0 + tid;
    float4* qk = (float4*)(g_q + row * 16);
    float4* kk = (float4*)(g_k + row * 16);
    float4* vk = (float4*)(g_v + row * 16);
#pragma unroll
    for (int i = 0; i < 4; i++) {
        qk[i] = make_float4(aQ[4*i+0]*qscale, aQ[4*i+1]*qscale,
                            aQ[4*i+2]*qscale, aQ[4*i+3]*qscale);
        kk[i] = make_float4(aK[4*i+0], aK[4*i+1], aK[4*i+2], aK[4*i+3]);
        vk[i] = make_float4(aV[4*i+0], aV[4*i+1], aV[4*i+2], aV[4*i+3]);
    }
}

// ---------------------------------------------------------------------------
// Kernel 2: causal flash attention.
// Grid: (T/32, B) = (128, 4). Block = 128 threads = 32 queries x 4 key-lanes.
// Each lane accumulates exp2(score) sums over a strided key subset; lanes of
// the same query are combined with shfl_xor. No running max: q is pre-scaled
// to log2 domain and scores are bounded (|s| << 127), so raw ex2 is safe.
// Keys staged 128 at a time into smem, rows padded to 20 floats.
// ---------------------------------------------------------------------------
#define KTILE 128
#define KPAD  20

__global__ __launch_bounds__(128, 4)
void attn_kernel(float* __restrict__ out) {
    __shared__ float sk[KTILE * KPAD];
    __shared__ float sv[KTILE * KPAD];

    const int tid = threadIdx.x;
    const int qi  = tid >> 2;
    const int kj  = tid & 3;
    const int b   = blockIdx.y;
    const int q_start = blockIdx.x * 32;
    const int gq  = q_start + qi;

    // load this thread's query row
    float q[16];
    {
        const float4* q4 = (const float4*)(g_q + ((long)b * T_ + gq) * 16);
#pragma unroll
        for (int i = 0; i < 4; i++) {
            float4 t = q4[i];
            q[4*i+0] = t.x; q[4*i+1] = t.y; q[4*i+2] = t.z; q[4*i+3] = t.w;
        }
    }

    float acc[16];
#pragma unroll
    for (int h = 0; h < 16; h++) acc[h] = 0.f;
    float l = 0.f;

    const int n_keys = q_start + 32;  // block needs keys [0, q_start+31]
    const float4* kg = (const float4*)(g_k + (long)b * T_ * 16);
    const float4* vg = (const float4*)(g_v + (long)b * T_ * 16);

    for (int t0 = 0; t0 < n_keys; t0 += KTILE) {
        const int nk = min(KTILE, n_keys - t0);

        // stage k/v tile (coalesced float4 loads)
        for (int i = tid; i < nk * 4; i += 128) {
            int r  = i >> 2;
            int c4 = i & 3;
            float4 kv = kg[(t0 + r) * 4 + c4];
            float4 vv = vg[(t0 + r) * 4 + c4];
            float* dk = &sk[r * KPAD + c4 * 4];
            dk[0] = kv.x; dk[1] = kv.y; dk[2] = kv.z; dk[3] = kv.w;
            float* dv = &sv[r * KPAD + c4 * 4];
            dv[0] = vv.x; dv[1] = vv.y; dv[2] = vv.z; dv[3] = vv.w;
        }
        __syncthreads();

        const int jmax = min(nk, gq - t0 + 1);  // causal: key t0+j <= gq
        for (int j = kj; j < jmax; j += 4) {
            const float* kr = &sk[j * KPAD];
            // dot with 4 independent partials for ILP
            float s0 = q[0] * kr[0], s1 = q[1] * kr[1];
            float s2 = q[2] * kr[2], s3 = q[3] * kr[3];
#pragma unroll
            for (int h = 4; h < 16; h += 4) {
                s0 = fmaf(q[h+0], kr[h+0], s0);
                s1 = fmaf(q[h+1], kr[h+1], s1);
                s2 = fmaf(q[h+2], kr[h+2], s2);
                s3 = fmaf(q[h+3], kr[h+3], s3);
            }
            float p = ex2((s0 + s1) + (s2 + s3));
            l += p;
            const float* vr = &sv[j * KPAD];
#pragma unroll
            for (int h = 0; h < 16; h++)
                acc[h] = fmaf(p, vr[h], acc[h]);
        }
        __syncthreads();
    }

    // combine the 4 key-lanes of each query (groups of 4 lanes in a warp)
#pragma unroll
    for (int off = 1; off <= 2; off <<= 1) {
        l += __shfl_xor_sync(0xffffffffu, l, off);
#pragma unroll
        for (int h = 0; h < 16; h++)
            acc[h] += __shfl_xor_sync(0xffffffffu, acc[h], off);
    }

    if (kj == 0) {
        float inv = 1.0f / l;
        float4* o4 = (float4*)(out + ((long)b * T_ + gq) * 16);
#pragma unroll
        for (int i = 0; i < 4; i++)
            o4[i] = make_float4(acc[4*i+0]*inv, acc[4*i+1]*inv,
                                acc[4*i+2]*inv, acc[4*i+3]*inv);
    }
}

extern "C" void kernel_launch(void* const* d_in, const int* in_sizes, int n_in,
                              void* d_out, int out_size) {
    const float* x  = (const float*)d_in[0];
    const float* Wk = (const float*)d_in[1];
    const float* Wq = (const float*)d_in[2];
    const float* Wv = (const float*)d_in[3];
    float* out = (float*)d_out;

    proj_kernel<<<BT_ / 128, 128>>>(x, Wk, Wq, Wv);
    attn_kernel<<<dim3(T_ / 32, B_), 128>>>(out);
}

// round 2
// speedup vs baseline: 1.2174x; 1.2174x over previous
#include <cuda_runtime.h>
#include <cstdint>

// Problem: B=4, T=4096, C=384 (n_embd), H=16 (head_size)
// out[b,t,:] = softmax_causal( (x@Wq)(x@Wk)^T / sqrt(H) ) @ (x@Wv)

#define B_   4
#define T_   4096
#define C_   384
#define H_   16
#define BT_  (B_ * T_)

// Scratch: q (pre-scaled by H^-0.5 * log2 e), k, v — [B*T,16] fp32
__device__ float g_q[BT_ * H_];
__device__ float g_k[BT_ * H_];
__device__ float g_v[BT_ * H_];

// ---------------- packed f32x2 helpers (sm_10x FFMA2 path) ----------------
__device__ __forceinline__ float ex2(float x) {
    float y; asm("ex2.approx.ftz.f32 %0, %1;" : "=f"(y) : "f"(x)); return y;
}
__device__ __forceinline__ double pk2(float lo, float hi) {
    double d; asm("mov.b64 %0, {%1, %2};" : "=d"(d) : "f"(lo), "f"(hi)); return d;
}
__device__ __forceinline__ void upk2(double d, float& lo, float& hi) {
    asm("mov.b64 {%0, %1}, %2;" : "=f"(lo), "=f"(hi) : "d"(d));
}
__device__ __forceinline__ double fma2(double a, double b, double c) {
    double d; asm("fma.rn.f32x2 %0, %1, %2, %3;" : "=d"(d) : "d"(a), "d"(b), "d"(c)); return d;
}
__device__ __forceinline__ double mul2(double a, double b) {
    double d; asm("mul.rn.f32x2 %0, %1, %2;" : "=d"(d) : "d"(a), "d"(b)); return d;
}
__device__ __forceinline__ double add2(double a, double b) {
    double d; asm("add.rn.f32x2 %0, %1, %2;" : "=d"(d) : "d"(a), "d"(b)); return d;
}
__device__ __forceinline__ void cp16(unsigned s, const void* g) {
    asm volatile("cp.async.cg.shared.global [%0], [%1], 16;" :: "r"(s), "l"(g));
}

// ---------------------------------------------------------------------------
// Kernel 1: fused QKV projection (packed FFMA2).
// Block = 128 threads, one token row each. x chunk [128x64] + W chunks staged
// in smem. q pre-scaled to log2 domain.
// ---------------------------------------------------------------------------
__global__ __launch_bounds__(128, 1)
void proj_kernel(const float* __restrict__ x,
                 const float* __restrict__ Wk,
                 const float* __restrict__ Wq,
                 const float* __restrict__ Wv) {
    __shared__ float sx[128 * 65];
    __shared__ float swk[64 * 16];
    __shared__ float swq[64 * 16];
    __shared__ float swv[64 * 16];

    const int tid = threadIdx.x;
    const long row0 = (long)blockIdx.x * 128;

    double aK[8], aQ[8], aV[8];
#pragma unroll
    for (int i = 0; i < 8; i++) { aK[i] = 0.0; aQ[i] = 0.0; aV[i] = 0.0; }

    const float4* xg = (const float4*)x;   // row stride = 96 float4

    for (int cc = 0; cc < 6; cc++) {
        for (int i = tid; i < 128 * 16; i += 128) {
            int r = i >> 4, c4 = i & 15;
            float4 v = xg[(row0 + r) * 96 + cc * 16 + c4];
            float* d = &sx[r * 65 + c4 * 4];
            d[0] = v.x; d[1] = v.y; d[2] = v.z; d[3] = v.w;
        }
        for (int i = tid; i < 256; i += 128) {
            ((float4*)swk)[i] = ((const float4*)(Wk + cc * 1024))[i];
            ((float4*)swq)[i] = ((const float4*)(Wq + cc * 1024))[i];
            ((float4*)swv)[i] = ((const float4*)(Wv + cc * 1024))[i];
        }
        __syncthreads();

        const float* xr = &sx[tid * 65];
#pragma unroll 4
        for (int c = 0; c < 64; c++) {
            float xv = xr[c];
            double xv2 = pk2(xv, xv);
            const double2* wk2 = (const double2*)&swk[c * 16];
            const double2* wq2 = (const double2*)&swq[c * 16];
            const double2* wv2 = (const double2*)&swv[c * 16];
#pragma unroll
            for (int m = 0; m < 4; m++) {
                double2 k = wk2[m], q = wq2[m], v = wv2[m];
                aK[2*m+0] = fma2(xv2, k.x, aK[2*m+0]);
                aK[2*m+1] = fma2(xv2, k.y, aK[2*m+1]);
                aQ[2*m+0] = fma2(xv2, q.x, aQ[2*m+0]);
                aQ[2*m+1] = fma2(xv2, q.y, aQ[2*m+1]);
                aV[2*m+0] = fma2(xv2, v.x, aV[2*m+0]);
                aV[2*m+1] = fma2(xv2, v.y, aV[2*m+1]);
            }
        }
        __syncthreads();
    }

    const float qscale = 0.25f * 1.4426950408889634f;  // H^-0.5 * log2(e)
    const double qs2 = pk2(qscale, qscale);
    const long row = row0 + tid;
    double2* qd = (double2*)(g_q + row * 16);
    double2* kd = (double2*)(g_k + row * 16);
    double2* vd = (double2*)(g_v + row * 16);
#pragma unroll
    for (int m = 0; m < 4; m++) {
        double2 t;
        t.x = mul2(aQ[2*m+0], qs2); t.y = mul2(aQ[2*m+1], qs2);
        qd[m] = t;
        t.x = aK[2*m+0]; t.y = aK[2*m+1]; kd[m] = t;
        t.x = aV[2*m+0]; t.y = aV[2*m+1]; vd[m] = t;
    }
}

// ---------------------------------------------------------------------------
// Kernel 2: causal flash attention.
// Grid (128, 4), block 128 = 32 queries x 4 key-lanes. Heavy-first tile map.
// cp.async double-buffered k/v tiles; full tiles (constant bound 128) split
// from the single diagonal tile (per-query bound). Packed FFMA2 inner loop.
// ---------------------------------------------------------------------------
#define KTILE 128
#define KPAD  20
#define TILEF (KTILE * KPAD)

__global__ __launch_bounds__(128, 4)
void attn_kernel(float* __restrict__ out) {
    __shared__ float sk[2 * TILEF];
    __shared__ float sv[2 * TILEF];

    const int tid = threadIdx.x;
    const int qi  = tid >> 2;
    const int kj  = tid & 3;
    const int b   = blockIdx.y;
    const int tile = (int)gridDim.x - 1 - (int)blockIdx.x;  // heavy blocks first
    const int q_start = tile * 32;
    const int gq  = q_start + qi;

    // query row, packed
    double q2[8];
    {
        const double2* qs = (const double2*)(g_q + ((long)b * T_ + gq) * 16);
#pragma unroll
        for (int i = 0; i < 4; i++) { double2 t = qs[i]; q2[2*i] = t.x; q2[2*i+1] = t.y; }
    }

    double acc[8];
#pragma unroll
    for (int i = 0; i < 8; i++) acc[i] = 0.0;
    float l = 0.f;

    const int nfull = q_start >> 7;          // full 128-key tiles
    const int t0p   = nfull << 7;            // diagonal tile start
    const int nkp   = q_start + 32 - t0p;    // diagonal tile size (32..128)
    const int ntiles = nfull + 1;

    const float4* kg = (const float4*)(g_k + (long)b * T_ * 16);
    const float4* vg = (const float4*)(g_v + (long)b * T_ * 16);

    auto load_tile = [&](int buf, int t0, int nk) {
        unsigned sbk = (unsigned)__cvta_generic_to_shared(&sk[buf * TILEF]);
        unsigned sbv = (unsigned)__cvta_generic_to_shared(&sv[buf * TILEF]);
        for (int i = tid; i < nk * 4; i += 128) {
            int r = i >> 2, c4 = i & 3;
            unsigned off = (unsigned)(r * KPAD + c4 * 4) * 4u;
            cp16(sbk + off, kg + (long)(t0 + r) * 4 + c4);
            cp16(sbv + off, vg + (long)(t0 + r) * 4 + c4);
        }
        asm volatile("cp.async.commit_group;");
    };

    auto compute = [&](int buf, int jmax) {
        const float* kb = &sk[buf * TILEF];
        const float* vb = &sv[buf * TILEF];
#pragma unroll 4
        for (int j = kj; j < jmax; j += 4) {
            const double2* kr = (const double2*)(kb + j * KPAD);
            double2 k0 = kr[0], k1 = kr[1], k2 = kr[2], k3 = kr[3];
            double sa = mul2(q2[0], k0.x);
            sa = fma2(q2[2], k1.x, sa);
            sa = fma2(q2[4], k2.x, sa);
            sa = fma2(q2[6], k3.x, sa);
            double sb = mul2(q2[1], k0.y);
            sb = fma2(q2[3], k1.y, sb);
            sb = fma2(q2[5], k2.y, sb);
            sb = fma2(q2[7], k3.y, sb);
            double sc = add2(sa, sb);
            float lo, hi; upk2(sc, lo, hi);
            float p = ex2(lo + hi);
            l += p;
            double p2 = pk2(p, p);
            const double2* vr = (const double2*)(vb + j * KPAD);
            double2 v0 = vr[0], v1 = vr[1], v2 = vr[2], v3 = vr[3];
            acc[0] = fma2(p2, v0.x, acc[0]); acc[1] = fma2(p2, v0.y, acc[1]);
            acc[2] = fma2(p2, v1.x, acc[2]); acc[3] = fma2(p2, v1.y, acc[3]);
            acc[4] = fma2(p2, v2.x, acc[4]); acc[5] = fma2(p2, v2.y, acc[5]);
            acc[6] = fma2(p2, v3.x, acc[6]); acc[7] = fma2(p2, v3.y, acc[7]);
        }
    };

    load_tile(0, 0, (0 < nfull) ? KTILE : nkp);

    for (int t = 0; t < ntiles; t++) {
        if (t + 1 < ntiles) {
            load_tile((t + 1) & 1, (t + 1) * KTILE, (t + 1 < nfull) ? KTILE : nkp);
            asm volatile("cp.async.wait_group 1;");
        } else {
            asm volatile("cp.async.wait_group 0;");
        }
        __syncthreads();
        if (t < nfull) {
            compute(t & 1, KTILE);
        } else {
            compute(t & 1, gq - t0p + 1);   // diagonal tile: causal bound
        }
        __syncthreads();
    }

    // combine the 4 key-lanes of each query
#pragma unroll
    for (int off = 1; off <= 2; off <<= 1) {
        l += __shfl_xor_sync(0xffffffffu, l, off);
#pragma unroll
        for (int i = 0; i < 8; i++)
            acc[i] = add2(acc[i], __shfl_xor_sync(0xffffffffu, acc[i], off));
    }

    if (kj == 0) {
        float inv = 1.0f / l;
        float o[16];
#pragma unroll
        for (int i = 0; i < 8; i++) upk2(acc[i], o[2*i], o[2*i+1]);
        float4* o4 = (float4*)(out + ((long)b * T_ + gq) * 16);
#pragma unroll
        for (int i = 0; i < 4; i++)
            o4[i] = make_float4(o[4*i+0]*inv, o[4*i+1]*inv, o[4*i+2]*inv, o[4*i+3]*inv);
    }
}

extern "C" void kernel_launch(void* const* d_in, const int* in_sizes, int n_in,
                              void* d_out, int out_size) {
    const float* x  = (const float*)d_in[0];
    const float* Wk = (const float*)d_in[1];
    const float* Wq = (const float*)d_in[2];
    const float* Wv = (const float*)d_in[3];
    float* out = (float*)d_out;

    proj_kernel<<<BT_ / 128, 128>>>(x, Wk, Wq, Wv);
    attn_kernel<<<dim3(T_ / 32, B_), 128>>>(out);
}

// round 3
// speedup vs baseline: 1.3012x; 1.0688x over previous
#include <cuda_runtime.h>
#include <cstdint>

// Problem: B=4, T=4096, C=384 (n_embd), H=16 (head_size)
// out[b,t,:] = softmax_causal( (x@Wq)(x@Wk)^T / sqrt(H) ) @ (x@Wv)

#define B_   4
#define T_   4096
#define C_   384
#define H_   16
#define BT_  (B_ * T_)

__device__ float g_q[BT_ * H_];   // pre-scaled by H^-0.5 * log2(e)
__device__ float g_k[BT_ * H_];
__device__ float g_v[BT_ * H_];

// ---------------- packed f32x2 helpers ----------------
__device__ __forceinline__ float ex2(float x) {
    float y; asm("ex2.approx.ftz.f32 %0, %1;" : "=f"(y) : "f"(x)); return y;
}
__device__ __forceinline__ double pk2(float lo, float hi) {
    double d; asm("mov.b64 %0, {%1, %2};" : "=d"(d) : "f"(lo), "f"(hi)); return d;
}
__device__ __forceinline__ void upk2(double d, float& lo, float& hi) {
    asm("mov.b64 {%0, %1}, %2;" : "=f"(lo), "=f"(hi) : "d"(d));
}
__device__ __forceinline__ double fma2(double a, double b, double c) {
    double d; asm("fma.rn.f32x2 %0, %1, %2, %3;" : "=d"(d) : "d"(a), "d"(b), "d"(c)); return d;
}
__device__ __forceinline__ double mul2(double a, double b) {
    double d; asm("mul.rn.f32x2 %0, %1, %2;" : "=d"(d) : "d"(a), "d"(b)); return d;
}
__device__ __forceinline__ double add2(double a, double b) {
    double d; asm("add.rn.f32x2 %0, %1, %2;" : "=d"(d) : "d"(a), "d"(b)); return d;
}
__device__ __forceinline__ void cp16(unsigned s, const void* g) {
    asm volatile("cp.async.cg.shared.global [%0], [%1], 16;" :: "r"(s), "l"(g));
}

// ---------------------------------------------------------------------------
// Kernel 1: fused QKV projection. Block = 256 threads: 128 rows x 2 C-halves.
// Each half processes 32 of the 64 staged columns per chunk; partials combined
// through smem at the end. q pre-scaled to log2 domain.
// ---------------------------------------------------------------------------
__global__ __launch_bounds__(256, 1)
void proj_kernel(const float* __restrict__ x,
                 const float* __restrict__ Wk,
                 const float* __restrict__ Wq,
                 const float* __restrict__ Wv) {
    __shared__ __align__(16) float sx[128 * 65];
    __shared__ __align__(16) float sw[3][64 * 16];

    const int tid  = threadIdx.x;
    const int row  = tid & 127;
    const int half = tid >> 7;
    const long row0 = (long)blockIdx.x * 128;

    double aK[8], aQ[8], aV[8];
#pragma unroll
    for (int i = 0; i < 8; i++) { aK[i] = 0.0; aQ[i] = 0.0; aV[i] = 0.0; }

    const float4* xg = (const float4*)x;   // row stride = 96 float4
    const float4* wg[3] = { (const float4*)Wk, (const float4*)Wq, (const float4*)Wv };

    for (int cc = 0; cc < 6; cc++) {
        // stage x[128][64]: 2048 float4 by 256 threads
        for (int i = tid; i < 2048; i += 256) {
            int r = i >> 4, c4 = i & 15;
            float4 v = xg[(row0 + r) * 96 + cc * 16 + c4];
            float* d = &sx[r * 65 + c4 * 4];
            d[0] = v.x; d[1] = v.y; d[2] = v.z; d[3] = v.w;
        }
        // stage W chunks: 3 x 256 float4
        for (int i = tid; i < 768; i += 256) {
            int m = i >> 8, j = i & 255;
            ((float4*)sw[m])[j] = wg[m][cc * 256 + j];
        }
        __syncthreads();

        const float* xr = &sx[row * 65 + half * 32];
        const int cbase = half * 32;
#pragma unroll 4
        for (int c = 0; c < 32; c++) {
            float xv = xr[c];
            double xv2 = pk2(xv, xv);
            const double2* wk2 = (const double2*)&sw[0][(cbase + c) * 16];
            const double2* wq2 = (const double2*)&sw[1][(cbase + c) * 16];
            const double2* wv2 = (const double2*)&sw[2][(cbase + c) * 16];
#pragma unroll
            for (int m = 0; m < 4; m++) {
                double2 k = wk2[m], q = wq2[m], v = wv2[m];
                aK[2*m+0] = fma2(xv2, k.x, aK[2*m+0]);
                aK[2*m+1] = fma2(xv2, k.y, aK[2*m+1]);
                aQ[2*m+0] = fma2(xv2, q.x, aQ[2*m+0]);
                aQ[2*m+1] = fma2(xv2, q.y, aQ[2*m+1]);
                aV[2*m+0] = fma2(xv2, v.x, aV[2*m+0]);
                aV[2*m+1] = fma2(xv2, v.y, aV[2*m+1]);
            }
        }
        __syncthreads();
    }

    // combine halves via smem (reuse sx: 128 rows x 24 doubles = 24.6 KB)
    double* sp = (double*)sx;
    if (half == 1) {
#pragma unroll
        for (int i = 0; i < 8; i++) {
            sp[row * 24 + i]      = aK[i];
            sp[row * 24 + 8 + i]  = aQ[i];
            sp[row * 24 + 16 + i] = aV[i];
        }
    }
    __syncthreads();
    if (half == 0) {
        const float qscale = 0.25f * 1.4426950408889634f;  // H^-0.5 * log2(e)
        const double qs2 = pk2(qscale, qscale);
        const long r = row0 + row;
        double* qd = (double*)(g_q + r * 16);
        double* kd = (double*)(g_k + r * 16);
        double* vd = (double*)(g_v + r * 16);
#pragma unroll
        for (int i = 0; i < 8; i++) {
            kd[i] = add2(aK[i], sp[row * 24 + i]);
            qd[i] = mul2(add2(aQ[i], sp[row * 24 + 8 + i]), qs2);
            vd[i] = add2(aV[i], sp[row * 24 + 16 + i]);
        }
    }
}

// ---------------------------------------------------------------------------
// Kernel 2: causal flash attention, register-blocked.
// Grid (128, 4), block 128 = 8 q-slots x 16 key-lanes; each thread owns 4
// queries. k/v tiles in smem laid out [chunk][row] (16B stride, conflict-free
// LDS.128, broadcast across q-slots). cp.async double-buffered. Heavy-first.
// ---------------------------------------------------------------------------
#define KT 128

__global__ __launch_bounds__(128, 2)
void attn_kernel(float* __restrict__ out) {
    __shared__ __align__(16) float4 sk4[2][4][KT];
    __shared__ __align__(16) float4 sv4[2][4][KT];

    const int tid = threadIdx.x;
    const int kj  = tid & 15;        // key lane
    const int qs  = tid >> 4;        // q-slot (0..7)
    const int b   = blockIdx.y;
    const int tile = (int)gridDim.x - 1 - (int)blockIdx.x;   // heavy-first
    const int q_start = tile * 32;
    const int gq0 = q_start + qs * 4;

    // 4 query rows in packed registers
    double q2[4][8];
#pragma unroll
    for (int m = 0; m < 4; m++) {
        const double2* qsrc = (const double2*)(g_q + ((long)b * T_ + gq0 + m) * 16);
#pragma unroll
        for (int i = 0; i < 4; i++) { double2 t = qsrc[i]; q2[m][2*i] = t.x; q2[m][2*i+1] = t.y; }
    }

    double acc[4][8];
#pragma unroll
    for (int m = 0; m < 4; m++)
#pragma unroll
        for (int i = 0; i < 8; i++) acc[m][i] = 0.0;
    float l[4] = {0.f, 0.f, 0.f, 0.f};

    const int n_keys = q_start + 32;
    const int nfull  = q_start >> 7;       // full 128-key tiles
    const int t0p    = nfull << 7;         // diagonal tile start
    const int nkp    = n_keys - t0p;       // diagonal tile keys (32..128)
    const int ntiles = nfull + 1;

    const float4* kg = (const float4*)(g_k + (long)b * T_ * 16);
    const float4* vg = (const float4*)(g_v + (long)b * T_ * 16);

    auto load_tile = [&](int buf, int t0, int nk) {
        for (int i = tid; i < nk * 4; i += 128) {
            int r = i >> 2, c = i & 3;
            cp16((unsigned)__cvta_generic_to_shared(&sk4[buf][c][r]), kg + (long)(t0 + r) * 4 + c);
            cp16((unsigned)__cvta_generic_to_shared(&sv4[buf][c][r]), vg + (long)(t0 + r) * 4 + c);
        }
        asm volatile("cp.async.commit_group;");
    };

    load_tile(0, 0, (nfull > 0) ? KT : nkp);

    for (int t = 0; t < ntiles; t++) {
        if (t + 1 < ntiles) {
            load_tile((t + 1) & 1, (t + 1) * KT, (t + 1 < nfull) ? KT : nkp);
            asm volatile("cp.async.wait_group 1;");
        } else {
            asm volatile("cp.async.wait_group 0;");
        }
        __syncthreads();

        const int buf = t & 1;
        if (t < nfull) {
            // full tile: every key valid for every query
#pragma unroll 2
            for (int j = kj; j < KT; j += 16) {
                float4 k0 = sk4[buf][0][j], k1 = sk4[buf][1][j];
                float4 k2 = sk4[buf][2][j], k3 = sk4[buf][3][j];
                double2 K0 = *(double2*)&k0, K1 = *(double2*)&k1;
                double2 K2 = *(double2*)&k2, K3 = *(double2*)&k3;
                float p[4];
#pragma unroll
                for (int m = 0; m < 4; m++) {
                    double sa = mul2(q2[m][0], K0.x);
                    sa = fma2(q2[m][2], K1.x, sa);
                    sa = fma2(q2[m][4], K2.x, sa);
                    sa = fma2(q2[m][6], K3.x, sa);
                    double sb = mul2(q2[m][1], K0.y);
                    sb = fma2(q2[m][3], K1.y, sb);
                    sb = fma2(q2[m][5], K2.y, sb);
                    sb = fma2(q2[m][7], K3.y, sb);
                    float lo, hi; upk2(add2(sa, sb), lo, hi);
                    p[m] = ex2(lo + hi);
                    l[m] += p[m];
                }
                float4 v0 = sv4[buf][0][j], v1 = sv4[buf][1][j];
                float4 v2 = sv4[buf][2][j], v3 = sv4[buf][3][j];
                double2 V0 = *(double2*)&v0, V1 = *(double2*)&v1;
                double2 V2 = *(double2*)&v2, V3 = *(double2*)&v3;
#pragma unroll
                for (int m = 0; m < 4; m++) {
                    double p2 = pk2(p[m], p[m]);
                    acc[m][0] = fma2(p2, V0.x, acc[m][0]);
                    acc[m][1] = fma2(p2, V0.y, acc[m][1]);
                    acc[m][2] = fma2(p2, V1.x, acc[m][2]);
                    acc[m][3] = fma2(p2, V1.y, acc[m][3]);
                    acc[m][4] = fma2(p2, V2.x, acc[m][4]);
                    acc[m][5] = fma2(p2, V2.y, acc[m][5]);
                    acc[m][6] = fma2(p2, V3.x, acc[m][6]);
                    acc[m][7] = fma2(p2, V3.y, acc[m][7]);
                }
            }
        } else {
            // diagonal tile: per-query causal predication
            for (int j = kj; j < nkp; j += 16) {
                const int key = t0p + j;
                float4 k0 = sk4[buf][0][j], k1 = sk4[buf][1][j];
                float4 k2 = sk4[buf][2][j], k3 = sk4[buf][3][j];
                double2 K0 = *(double2*)&k0, K1 = *(double2*)&k1;
                double2 K2 = *(double2*)&k2, K3 = *(double2*)&k3;
                float p[4];
#pragma unroll
                for (int m = 0; m < 4; m++) {
                    double sa = mul2(q2[m][0], K0.x);
                    sa = fma2(q2[m][2], K1.x, sa);
                    sa = fma2(q2[m][4], K2.x, sa);
                    sa = fma2(q2[m][6], K3.x, sa);
                    double sb = mul2(q2[m][1], K0.y);
                    sb = fma2(q2[m][3], K1.y, sb);
                    sb = fma2(q2[m][5], K2.y, sb);
                    sb = fma2(q2[m][7], K3.y, sb);
                    float lo, hi; upk2(add2(sa, sb), lo, hi);
                    p[m] = (key <= gq0 + m) ? ex2(lo + hi) : 0.f;
                    l[m] += p[m];
                }
                float4 v0 = sv4[buf][0][j], v1 = sv4[buf][1][j];
                float4 v2 = sv4[buf][2][j], v3 = sv4[buf][3][j];
                double2 V0 = *(double2*)&v0, V1 = *(double2*)&v1;
                double2 V2 = *(double2*)&v2, V3 = *(double2*)&v3;
#pragma unroll
                for (int m = 0; m < 4; m++) {
                    double p2 = pk2(p[m], p[m]);
                    acc[m][0] = fma2(p2, V0.x, acc[m][0]);
                    acc[m][1] = fma2(p2, V0.y, acc[m][1]);
                    acc[m][2] = fma2(p2, V1.x, acc[m][2]);
                    acc[m][3] = fma2(p2, V1.y, acc[m][3]);
                    acc[m][4] = fma2(p2, V2.x, acc[m][4]);
                    acc[m][5] = fma2(p2, V2.y, acc[m][5]);
                    acc[m][6] = fma2(p2, V3.x, acc[m][6]);
                    acc[m][7] = fma2(p2, V3.y, acc[m][7]);
                }
            }
        }
        __syncthreads();
    }

    // reduce across the 16 key-lanes (stays within half-warp)
#pragma unroll
    for (int off = 1; off <= 8; off <<= 1) {
#pragma unroll
        for (int m = 0; m < 4; m++) {
            l[m] += __shfl_xor_sync(0xffffffffu, l[m], off);
#pragma unroll
            for (int i = 0; i < 8; i++)
                acc[m][i] = add2(acc[m][i], __shfl_xor_sync(0xffffffffu, acc[m][i], off));
        }
    }

    if (kj == 0) {
#pragma unroll
        for (int m = 0; m < 4; m++) {
            float inv = 1.0f / l[m];
            float o[16];
#pragma unroll
            for (int i = 0; i < 8; i++) upk2(acc[m][i], o[2*i], o[2*i+1]);
            float4* o4 = (float4*)(out + ((long)b * T_ + gq0 + m) * 16);
#pragma unroll
            for (int i = 0; i < 4; i++)
                o4[i] = make_float4(o[4*i+0]*inv, o[4*i+1]*inv, o[4*i+2]*inv, o[4*i+3]*inv);
        }
    }
}

extern "C" void kernel_launch(void* const* d_in, const int* in_sizes, int n_in,
                              void* d_out, int out_size) {
    const float* x  = (const float*)d_in[0];
    const float* Wk = (const float*)d_in[1];
    const float* Wq = (const float*)d_in[2];
    const float* Wv = (const float*)d_in[3];
    float* out = (float*)d_out;

    proj_kernel<<<BT_ / 128, 256>>>(x, Wk, Wq, Wv);
    attn_kernel<<<dim3(T_ / 32, B_), 128>>>(out);
}

// round 4
// speedup vs baseline: 1.4605x; 1.1224x over previous
#include <cuda_runtime.h>
#include <cstdint>

// Problem: B=4, T=4096, C=384 (n_embd), H=16 (head_size)
// out[b,t,:] = softmax_causal( (x@Wq)(x@Wk)^T / sqrt(H) ) @ (x@Wv)

#define B_     4
#define T_     4096
#define C_     384
#define H_     16
#define BT_    (B_ * T_)
#define SPLITS 4

__device__ float g_q[BT_ * H_];   // pre-scaled by H^-0.5 * log2(e)
__device__ float g_k[BT_ * H_];
__device__ float g_v[BT_ * H_];
__device__ float g_pacc[SPLITS * BT_ * H_];  // split partial numerators
__device__ float g_pl[SPLITS * BT_];         // split partial denominators

// ---------------- packed f32x2 helpers ----------------
__device__ __forceinline__ float ex2(float x) {
    float y; asm("ex2.approx.ftz.f32 %0, %1;" : "=f"(y) : "f"(x)); return y;
}
__device__ __forceinline__ double pk2(float lo, float hi) {
    double d; asm("mov.b64 %0, {%1, %2};" : "=d"(d) : "f"(lo), "f"(hi)); return d;
}
__device__ __forceinline__ void upk2(double d, float& lo, float& hi) {
    asm("mov.b64 {%0, %1}, %2;" : "=f"(lo), "=f"(hi) : "d"(d));
}
__device__ __forceinline__ double fma2(double a, double b, double c) {
    double d; asm("fma.rn.f32x2 %0, %1, %2, %3;" : "=d"(d) : "d"(a), "d"(b), "d"(c)); return d;
}
__device__ __forceinline__ double mul2(double a, double b) {
    double d; asm("mul.rn.f32x2 %0, %1, %2;" : "=d"(d) : "d"(a), "d"(b)); return d;
}
__device__ __forceinline__ double add2(double a, double b) {
    double d; asm("add.rn.f32x2 %0, %1, %2;" : "=d"(d) : "d"(a), "d"(b)); return d;
}
__device__ __forceinline__ void cp16(unsigned s, const void* g) {
    asm volatile("cp.async.cg.shared.global [%0], [%1], 16;" :: "r"(s), "l"(g));
}

// ---------------------------------------------------------------------------
// Kernel 1: fused QKV projection.
// Block = 256 threads = 64 rows x 4 C-quarters (quarter handles 16 of the 64
// staged columns per chunk -> 96 columns total). Partials combined via smem
// (overlaid on the staging buffer). Grid = 256 blocks.
// ---------------------------------------------------------------------------
__global__ __launch_bounds__(256, 2)
void proj_kernel(const float* __restrict__ x,
                 const float* __restrict__ Wk,
                 const float* __restrict__ Wq,
                 const float* __restrict__ Wv) {
    // staging: sx 64*65 floats (16.6KB) + sw 3*1024 floats (12.3KB) = 29KB
    // combine: 3 quarters * 64 rows * 24 doubles = 36.9KB   (overlaid)
    __shared__ __align__(16) char sbuf[3 * 64 * 24 * 8];
    float* sx = (float*)sbuf;                       // [64][65]
    float (*sw)[1024] = (float(*)[1024])(sbuf + 64 * 65 * 4);
    double* scomb = (double*)sbuf;                  // [3][64][24]

    const int tid = threadIdx.x;
    const int row = tid & 63;
    const int qtr = tid >> 6;          // 0..3
    const long row0 = (long)blockIdx.x * 64;

    double aK[8], aQ[8], aV[8];
#pragma unroll
    for (int i = 0; i < 8; i++) { aK[i] = 0.0; aQ[i] = 0.0; aV[i] = 0.0; }

    const float4* xg = (const float4*)x;   // row stride = 96 float4
    const float4* wg[3] = { (const float4*)Wk, (const float4*)Wq, (const float4*)Wv };

    for (int cc = 0; cc < 6; cc++) {
        for (int i = tid; i < 64 * 16; i += 256) {     // x tile 64x64
            int r = i >> 4, c4 = i & 15;
            float4 v = xg[(row0 + r) * 96 + cc * 16 + c4];
            float* d = &sx[r * 65 + c4 * 4];
            d[0] = v.x; d[1] = v.y; d[2] = v.z; d[3] = v.w;
        }
        for (int i = tid; i < 768; i += 256) {         // W chunks
            int m = i >> 8, j = i & 255;
            ((float4*)sw[m])[j] = wg[m][cc * 256 + j];
        }
        __syncthreads();

        const float* xr = &sx[row * 65 + qtr * 16];
        const int cbase = qtr * 16;
#pragma unroll 4
        for (int c = 0; c < 16; c++) {
            float xv = xr[c];
            double xv2 = pk2(xv, xv);
            const double2* wk2 = (const double2*)&sw[0][(cbase + c) * 16];
            const double2* wq2 = (const double2*)&sw[1][(cbase + c) * 16];
            const double2* wv2 = (const double2*)&sw[2][(cbase + c) * 16];
#pragma unroll
            for (int m = 0; m < 4; m++) {
                double2 k = wk2[m], q = wq2[m], v = wv2[m];
                aK[2*m+0] = fma2(xv2, k.x, aK[2*m+0]);
                aK[2*m+1] = fma2(xv2, k.y, aK[2*m+1]);
                aQ[2*m+0] = fma2(xv2, q.x, aQ[2*m+0]);
                aQ[2*m+1] = fma2(xv2, q.y, aQ[2*m+1]);
                aV[2*m+0] = fma2(xv2, v.x, aV[2*m+0]);
                aV[2*m+1] = fma2(xv2, v.y, aV[2*m+1]);
            }
        }
        __syncthreads();
    }

    // combine 4 quarters: 1..3 publish, 0 accumulates + writes
    if (qtr != 0) {
        double* d = &scomb[((qtr - 1) * 64 + row) * 24];
#pragma unroll
        for (int i = 0; i < 8; i++) {
            d[i] = aK[i]; d[8 + i] = aQ[i]; d[16 + i] = aV[i];
        }
    }
    __syncthreads();
    if (qtr == 0) {
        const float qscale = 0.25f * 1.4426950408889634f;  // H^-0.5 * log2(e)
        const double qs2 = pk2(qscale, qscale);
        const long r = row0 + row;
        double* qd = (double*)(g_q + r * 16);
        double* kd = (double*)(g_k + r * 16);
        double* vd = (double*)(g_v + r * 16);
#pragma unroll
        for (int i = 0; i < 8; i++) {
            double k = aK[i], q = aQ[i], v = aV[i];
#pragma unroll
            for (int s = 0; s < 3; s++) {
                const double* d = &scomb[(s * 64 + row) * 24];
                k = add2(k, d[i]); q = add2(q, d[8 + i]); v = add2(v, d[16 + i]);
            }
            kd[i] = k; qd[i] = mul2(q, qs2); vd[i] = v;
        }
    }
}

// ---------------------------------------------------------------------------
// Kernel 2: causal flash attention, split-K partials.
// Grid (128, 4, 4) = (q_tile, split, batch) = 2048 blocks. Block = 128
// threads = 32 queries x 4 key-lanes. Each block covers 1/4 of its tile's
// key range; writes partial (acc, l) to scratch. exp2-domain, no max
// tracking, so split combination is exact. cp.async double-buffered tiles.
// ---------------------------------------------------------------------------
#define KT 64

__global__ __launch_bounds__(128, 4)
void attn_kernel() {
    __shared__ __align__(16) float4 sk4[2][4][KT];
    __shared__ __align__(16) float4 sv4[2][4][KT];

    const int tid = threadIdx.x;
    const int qi  = tid >> 2;
    const int kj  = tid & 3;
    const int b   = blockIdx.z;
    const int split = blockIdx.y;
    const int tile  = (int)gridDim.x - 1 - (int)blockIdx.x;  // heavy-first
    const int q_start = tile * 32;
    const int gq  = q_start + qi;

    // query row, packed
    double q2[8];
    {
        const double2* qs = (const double2*)(g_q + ((long)b * T_ + gq) * 16);
#pragma unroll
        for (int i = 0; i < 4; i++) { double2 t = qs[i]; q2[2*i] = t.x; q2[2*i+1] = t.y; }
    }

    double acc[8];
#pragma unroll
    for (int i = 0; i < 8; i++) acc[i] = 0.0;
    float l = 0.f;

    const int n_keys = q_start + 32;
    const int len = (n_keys + SPLITS - 1) >> 2;
    const int kb  = split * len;
    const int ke  = min(kb + len, n_keys);

    const float4* kg = (const float4*)(g_k + (long)b * T_ * 16);
    const float4* vg = (const float4*)(g_v + (long)b * T_ * 16);

    auto load_tile = [&](int buf, int t0, int nk) {
        for (int i = tid; i < nk * 4; i += 128) {
            int r = i >> 2, c = i & 3;
            cp16((unsigned)__cvta_generic_to_shared(&sk4[buf][c][r]), kg + (long)(t0 + r) * 4 + c);
            cp16((unsigned)__cvta_generic_to_shared(&sv4[buf][c][r]), vg + (long)(t0 + r) * 4 + c);
        }
        asm volatile("cp.async.commit_group;");
    };

    const int nt = (ke - kb + KT - 1) / KT;
    load_tile(0, kb, min(KT, ke - kb));

    for (int t = 0; t < nt; t++) {
        const int t0 = kb + t * KT;
        const int nk = min(KT, ke - t0);
        if (t + 1 < nt) {
            load_tile((t + 1) & 1, t0 + KT, min(KT, ke - t0 - KT));
            asm volatile("cp.async.wait_group 1;");
        } else {
            asm volatile("cp.async.wait_group 0;");
        }
        __syncthreads();

        const int buf = t & 1;
#pragma unroll 2
        for (int j = kj; j < nk; j += 4) {
            const int key = t0 + j;
            float4 k0 = sk4[buf][0][j], k1 = sk4[buf][1][j];
            float4 k2 = sk4[buf][2][j], k3 = sk4[buf][3][j];
            double2 K0 = *(double2*)&k0, K1 = *(double2*)&k1;
            double2 K2 = *(double2*)&k2, K3 = *(double2*)&k3;
            double sa = mul2(q2[0], K0.x);
            sa = fma2(q2[2], K1.x, sa);
            sa = fma2(q2[4], K2.x, sa);
            sa = fma2(q2[6], K3.x, sa);
            double sb = mul2(q2[1], K0.y);
            sb = fma2(q2[3], K1.y, sb);
            sb = fma2(q2[5], K2.y, sb);
            sb = fma2(q2[7], K3.y, sb);
            float lo, hi; upk2(add2(sa, sb), lo, hi);
            float p = (key <= gq) ? ex2(lo + hi) : 0.f;
            l += p;
            double p2 = pk2(p, p);
            float4 v0 = sv4[buf][0][j], v1 = sv4[buf][1][j];
            float4 v2 = sv4[buf][2][j], v3 = sv4[buf][3][j];
            double2 V0 = *(double2*)&v0, V1 = *(double2*)&v1;
            double2 V2 = *(double2*)&v2, V3 = *(double2*)&v3;
            acc[0] = fma2(p2, V0.x, acc[0]); acc[1] = fma2(p2, V0.y, acc[1]);
            acc[2] = fma2(p2, V1.x, acc[2]); acc[3] = fma2(p2, V1.y, acc[3]);
            acc[4] = fma2(p2, V2.x, acc[4]); acc[5] = fma2(p2, V2.y, acc[5]);
            acc[6] = fma2(p2, V3.x, acc[6]); acc[7] = fma2(p2, V3.y, acc[7]);
        }
        __syncthreads();
    }

    // combine the 4 key-lanes of each query (within quad)
#pragma unroll
    for (int off = 1; off <= 2; off <<= 1) {
        l += __shfl_xor_sync(0xffffffffu, l, off);
#pragma unroll
        for (int i = 0; i < 8; i++)
            acc[i] = add2(acc[i], __shfl_xor_sync(0xffffffffu, acc[i], off));
    }

    if (kj == 0) {
        const long prow = (long)split * BT_ + (long)b * T_ + gq;
        g_pl[prow] = l;
        float o[16];
#pragma unroll
        for (int i = 0; i < 8; i++) upk2(acc[i], o[2*i], o[2*i+1]);
        float4* p4 = (float4*)(g_pacc + prow * 16);
#pragma unroll
        for (int i = 0; i < 4; i++)
            p4[i] = make_float4(o[4*i+0], o[4*i+1], o[4*i+2], o[4*i+3]);
    }
}

// ---------------------------------------------------------------------------
// Kernel 3: combine split partials. One thread per output row.
// ---------------------------------------------------------------------------
__global__ __launch_bounds__(256)
void combine_kernel(float* __restrict__ out) {
    const int row = blockIdx.x * 256 + threadIdx.x;   // 0..BT_-1
    float l = 0.f;
#pragma unroll
    for (int s = 0; s < SPLITS; s++) l += g_pl[(long)s * BT_ + row];
    const float inv = 1.0f / l;

    float4* o4 = (float4*)out + (long)row * 4;
#pragma unroll
    for (int i = 0; i < 4; i++) {
        float4 a = make_float4(0.f, 0.f, 0.f, 0.f);
#pragma unroll
        for (int s = 0; s < SPLITS; s++) {
            float4 t = ((const float4*)g_pacc)[((long)s * BT_ + row) * 4 + i];
            a.x += t.x; a.y += t.y; a.z += t.z; a.w += t.w;
        }
        o4[i] = make_float4(a.x * inv, a.y * inv, a.z * inv, a.w * inv);
    }
}

extern "C" void kernel_launch(void* const* d_in, const int* in_sizes, int n_in,
                              void* d_out, int out_size) {
    const float* x  = (const float*)d_in[0];
    const float* Wk = (const float*)d_in[1];
    const float* Wq = (const float*)d_in[2];
    const float* Wv = (const float*)d_in[3];
    float* out = (float*)d_out;

    proj_kernel<<<BT_ / 64, 256>>>(x, Wk, Wq, Wv);
    attn_kernel<<<dim3(T_ / 32, SPLITS, B_), 128>>>();
    combine_kernel<<<BT_ / 256, 256>>>(out);
}

// round 5
// speedup vs baseline: 1.5042x; 1.0299x over previous
#include <cuda_runtime.h>
#include <cstdint>

// Problem: B=4, T=4096, C=384 (n_embd), H=16 (head_size)
// out[b,t,:] = softmax_causal( (x@Wq)(x@Wk)^T / sqrt(H) ) @ (x@Wv)

#define B_     4
#define T_     4096
#define C_     384
#define H_     16
#define BT_    (B_ * T_)
#define SPLITS 8

__device__ float g_q[BT_ * H_];   // pre-scaled by H^-0.5 * log2(e)
__device__ float g_k[BT_ * H_];
__device__ float g_v[BT_ * H_];
__device__ float g_pacc[SPLITS * BT_ * H_];  // split partial numerators
__device__ float g_pl[SPLITS * BT_];         // split partial denominators

// ---------------- packed f32x2 helpers ----------------
__device__ __forceinline__ float ex2(float x) {
    float y; asm("ex2.approx.ftz.f32 %0, %1;" : "=f"(y) : "f"(x)); return y;
}
__device__ __forceinline__ double pk2(float lo, float hi) {
    double d; asm("mov.b64 %0, {%1, %2};" : "=d"(d) : "f"(lo), "f"(hi)); return d;
}
__device__ __forceinline__ void upk2(double d, float& lo, float& hi) {
    asm("mov.b64 {%0, %1}, %2;" : "=f"(lo), "=f"(hi) : "d"(d));
}
__device__ __forceinline__ double fma2(double a, double b, double c) {
    double d; asm("fma.rn.f32x2 %0, %1, %2, %3;" : "=d"(d) : "d"(a), "d"(b), "d"(c)); return d;
}
__device__ __forceinline__ double mul2(double a, double b) {
    double d; asm("mul.rn.f32x2 %0, %1, %2;" : "=d"(d) : "d"(a), "d"(b)); return d;
}
__device__ __forceinline__ double add2(double a, double b) {
    double d; asm("add.rn.f32x2 %0, %1, %2;" : "=d"(d) : "d"(a), "d"(b)); return d;
}
__device__ __forceinline__ void cp16(unsigned s, const void* g) {
    asm volatile("cp.async.cg.shared.global [%0], [%1], 16;" :: "r"(s), "l"(g));
}

// ---------------------------------------------------------------------------
// Kernel 1: fused QKV projection.
// Block = 128 threads = 32 rows x 4 C-quarters (each quarter covers 96 of 384
// cols). Grid = 512 blocks. Partials merged via smem overlay.
// ---------------------------------------------------------------------------
__global__ __launch_bounds__(128, 6)
void proj_kernel(const float* __restrict__ x,
                 const float* __restrict__ Wk,
                 const float* __restrict__ Wq,
                 const float* __restrict__ Wv) {
    // staging: sx 32*65*4=8320B + sw 3*1024*4=12288B = 20608B
    // combine overlay: 3*32*24*8 = 18432B
    __shared__ __align__(16) char sbuf[20608];
    float* sx = (float*)sbuf;                         // [32][65]
    float (*sw)[1024] = (float(*)[1024])(sbuf + 32 * 65 * 4);
    double* scomb = (double*)sbuf;                    // [3][32][24]

    const int tid = threadIdx.x;
    const int row = tid & 31;
    const int qtr = tid >> 5;          // 0..3
    const long row0 = (long)blockIdx.x * 32;

    double aK[8], aQ[8], aV[8];
#pragma unroll
    for (int i = 0; i < 8; i++) { aK[i] = 0.0; aQ[i] = 0.0; aV[i] = 0.0; }

    const float4* xg = (const float4*)x;   // row stride = 96 float4
    const float4* wg[3] = { (const float4*)Wk, (const float4*)Wq, (const float4*)Wv };

    for (int cc = 0; cc < 6; cc++) {
        for (int i = tid; i < 32 * 16; i += 128) {     // x tile 32x64
            int r = i >> 4, c4 = i & 15;
            float4 v = xg[(row0 + r) * 96 + cc * 16 + c4];
            float* d = &sx[r * 65 + c4 * 4];
            d[0] = v.x; d[1] = v.y; d[2] = v.z; d[3] = v.w;
        }
        for (int i = tid; i < 768; i += 128) {         // W chunks 3 x [64][16]
            int m = i >> 8, j = i & 255;
            ((float4*)sw[m])[j] = wg[m][cc * 256 + j];
        }
        __syncthreads();

        const float* xr = &sx[row * 65 + qtr * 16];
        const int cbase = qtr * 16;
#pragma unroll 4
        for (int c = 0; c < 16; c++) {
            float xv = xr[c];
            double xv2 = pk2(xv, xv);
            const double2* wk2 = (const double2*)&sw[0][(cbase + c) * 16];
            const double2* wq2 = (const double2*)&sw[1][(cbase + c) * 16];
            const double2* wv2 = (const double2*)&sw[2][(cbase + c) * 16];
#pragma unroll
            for (int m = 0; m < 4; m++) {
                double2 k = wk2[m], q = wq2[m], v = wv2[m];
                aK[2*m+0] = fma2(xv2, k.x, aK[2*m+0]);
                aK[2*m+1] = fma2(xv2, k.y, aK[2*m+1]);
                aQ[2*m+0] = fma2(xv2, q.x, aQ[2*m+0]);
                aQ[2*m+1] = fma2(xv2, q.y, aQ[2*m+1]);
                aV[2*m+0] = fma2(xv2, v.x, aV[2*m+0]);
                aV[2*m+1] = fma2(xv2, v.y, aV[2*m+1]);
            }
        }
        __syncthreads();
    }

    // merge quarters: 1..3 publish, 0 accumulates + writes
    if (qtr != 0) {
        double* d = &scomb[((qtr - 1) * 32 + row) * 24];
#pragma unroll
        for (int i = 0; i < 8; i++) {
            d[i] = aK[i]; d[8 + i] = aQ[i]; d[16 + i] = aV[i];
        }
    }
    __syncthreads();
    if (qtr == 0) {
        const float qscale = 0.25f * 1.4426950408889634f;  // H^-0.5 * log2(e)
        const double qs2 = pk2(qscale, qscale);
        const long r = row0 + row;
        double* qd = (double*)(g_q + r * 16);
        double* kd = (double*)(g_k + r * 16);
        double* vd = (double*)(g_v + r * 16);
#pragma unroll
        for (int i = 0; i < 8; i++) {
            double k = aK[i], q = aQ[i], v = aV[i];
#pragma unroll
            for (int s = 0; s < 3; s++) {
                const double* d = &scomb[(s * 32 + row) * 24];
                k = add2(k, d[i]); q = add2(q, d[8 + i]); v = add2(v, d[16 + i]);
            }
            kd[i] = k; qd[i] = mul2(q, qs2); vd[i] = v;
        }
    }
}

// ---------------------------------------------------------------------------
// Kernel 2: causal flash attention, split-K partials.
// Grid (128, 8, 4) = 4096 blocks. Block = 128 threads = 32 q x 4 key-lanes.
// Splits whose range ends <= q_start take a predicate-free fast path.
// exp2-domain (no max) => split combining exact. cp.async double-buffered.
// ---------------------------------------------------------------------------
#define KT 64

__global__ __launch_bounds__(128, 6)
void attn_kernel() {
    __shared__ __align__(16) float4 sk4[2][4][KT];
    __shared__ __align__(16) float4 sv4[2][4][KT];

    const int tid = threadIdx.x;
    const int qi  = tid >> 2;
    const int kj  = tid & 3;
    const int b   = blockIdx.z;
    const int split = blockIdx.y;
    const int tile  = (int)gridDim.x - 1 - (int)blockIdx.x;  // heavy-first
    const int q_start = tile * 32;
    const int gq  = q_start + qi;

    const int n_keys = q_start + 32;
    const int len = (n_keys + SPLITS - 1) / SPLITS;
    const int kb  = split * len;
    const int ke  = min(kb + len, n_keys);

    double acc[8];
#pragma unroll
    for (int i = 0; i < 8; i++) acc[i] = 0.0;
    float l = 0.f;

    if (kb < ke) {
        // query row, packed
        double q2[8];
        {
            const double2* qs = (const double2*)(g_q + ((long)b * T_ + gq) * 16);
#pragma unroll
            for (int i = 0; i < 4; i++) { double2 t = qs[i]; q2[2*i] = t.x; q2[2*i+1] = t.y; }
        }

        const float4* kg = (const float4*)(g_k + (long)b * T_ * 16);
        const float4* vg = (const float4*)(g_v + (long)b * T_ * 16);

        auto load_tile = [&](int buf, int t0, int nk) {
            for (int i = tid; i < nk * 4; i += 128) {
                int r = i >> 2, c = i & 3;
                cp16((unsigned)__cvta_generic_to_shared(&sk4[buf][c][r]), kg + (long)(t0 + r) * 4 + c);
                cp16((unsigned)__cvta_generic_to_shared(&sv4[buf][c][r]), vg + (long)(t0 + r) * 4 + c);
            }
            asm volatile("cp.async.commit_group;");
        };

        const bool safe = (ke <= q_start);   // every key < every query in tile
        const int nt = (ke - kb + KT - 1) / KT;
        load_tile(0, kb, min(KT, ke - kb));

        for (int t = 0; t < nt; t++) {
            const int t0 = kb + t * KT;
            const int nk = min(KT, ke - t0);
            if (t + 1 < nt) {
                load_tile((t + 1) & 1, t0 + KT, min(KT, ke - t0 - KT));
                asm volatile("cp.async.wait_group 1;");
            } else {
                asm volatile("cp.async.wait_group 0;");
            }
            __syncthreads();

            const int buf = t & 1;
            if (safe) {
#pragma unroll 2
                for (int j = kj; j < nk; j += 4) {
                    float4 k0 = sk4[buf][0][j], k1 = sk4[buf][1][j];
                    float4 k2 = sk4[buf][2][j], k3 = sk4[buf][3][j];
                    double2 K0 = *(double2*)&k0, K1 = *(double2*)&k1;
                    double2 K2 = *(double2*)&k2, K3 = *(double2*)&k3;
                    double sa = mul2(q2[0], K0.x);
                    sa = fma2(q2[2], K1.x, sa);
                    sa = fma2(q2[4], K2.x, sa);
                    sa = fma2(q2[6], K3.x, sa);
                    double sb = mul2(q2[1], K0.y);
                    sb = fma2(q2[3], K1.y, sb);
                    sb = fma2(q2[5], K2.y, sb);
                    sb = fma2(q2[7], K3.y, sb);
                    float lo, hi; upk2(add2(sa, sb), lo, hi);
                    float p = ex2(lo + hi);
                    l += p;
                    double p2 = pk2(p, p);
                    float4 v0 = sv4[buf][0][j], v1 = sv4[buf][1][j];
                    float4 v2 = sv4[buf][2][j], v3 = sv4[buf][3][j];
                    double2 V0 = *(double2*)&v0, V1 = *(double2*)&v1;
                    double2 V2 = *(double2*)&v2, V3 = *(double2*)&v3;
                    acc[0] = fma2(p2, V0.x, acc[0]); acc[1] = fma2(p2, V0.y, acc[1]);
                    acc[2] = fma2(p2, V1.x, acc[2]); acc[3] = fma2(p2, V1.y, acc[3]);
                    acc[4] = fma2(p2, V2.x, acc[4]); acc[5] = fma2(p2, V2.y, acc[5]);
                    acc[6] = fma2(p2, V3.x, acc[6]); acc[7] = fma2(p2, V3.y, acc[7]);
                }
            } else {
#pragma unroll 2
                for (int j = kj; j < nk; j += 4) {
                    const int key = t0 + j;
                    float4 k0 = sk4[buf][0][j], k1 = sk4[buf][1][j];
                    float4 k2 = sk4[buf][2][j], k3 = sk4[buf][3][j];
                    double2 K0 = *(double2*)&k0, K1 = *(double2*)&k1;
                    double2 K2 = *(double2*)&k2, K3 = *(double2*)&k3;
                    double sa = mul2(q2[0], K0.x);
                    sa = fma2(q2[2], K1.x, sa);
                    sa = fma2(q2[4], K2.x, sa);
                    sa = fma2(q2[6], K3.x, sa);
                    double sb = mul2(q2[1], K0.y);
                    sb = fma2(q2[3], K1.y, sb);
                    sb = fma2(q2[5], K2.y, sb);
                    sb = fma2(q2[7], K3.y, sb);
                    float lo, hi; upk2(add2(sa, sb), lo, hi);
                    float p = (key <= gq) ? ex2(lo + hi) : 0.f;
                    l += p;
                    double p2 = pk2(p, p);
                    float4 v0 = sv4[buf][0][j], v1 = sv4[buf][1][j];
                    float4 v2 = sv4[buf][2][j], v3 = sv4[buf][3][j];
                    double2 V0 = *(double2*)&v0, V1 = *(double2*)&v1;
                    double2 V2 = *(double2*)&v2, V3 = *(double2*)&v3;
                    acc[0] = fma2(p2, V0.x, acc[0]); acc[1] = fma2(p2, V0.y, acc[1]);
                    acc[2] = fma2(p2, V1.x, acc[2]); acc[3] = fma2(p2, V1.y, acc[3]);
                    acc[4] = fma2(p2, V2.x, acc[4]); acc[5] = fma2(p2, V2.y, acc[5]);
                    acc[6] = fma2(p2, V3.x, acc[6]); acc[7] = fma2(p2, V3.y, acc[7]);
                }
            }
            __syncthreads();
        }
    }

    // combine the 4 key-lanes of each query (within quad)
#pragma unroll
    for (int off = 1; off <= 2; off <<= 1) {
        l += __shfl_xor_sync(0xffffffffu, l, off);
#pragma unroll
        for (int i = 0; i < 8; i++)
            acc[i] = add2(acc[i], __shfl_xor_sync(0xffffffffu, acc[i], off));
    }

    if (kj == 0) {
        const long prow = (long)split * BT_ + (long)b * T_ + gq;
        g_pl[prow] = l;
        float o[16];
#pragma unroll
        for (int i = 0; i < 8; i++) upk2(acc[i], o[2*i], o[2*i+1]);
        float4* p4 = (float4*)(g_pacc + prow * 16);
#pragma unroll
        for (int i = 0; i < 4; i++)
            p4[i] = make_float4(o[4*i+0], o[4*i+1], o[4*i+2], o[4*i+3]);
    }
}

// ---------------------------------------------------------------------------
// Kernel 3: combine split partials. One thread per output row.
// ---------------------------------------------------------------------------
__global__ __launch_bounds__(256)
void combine_kernel(float* __restrict__ out) {
    const int row = blockIdx.x * 256 + threadIdx.x;   // 0..BT_-1
    float l = 0.f;
#pragma unroll
    for (int s = 0; s < SPLITS; s++) l += g_pl[(long)s * BT_ + row];
    const float inv = 1.0f / l;

    float4* o4 = (float4*)out + (long)row * 4;
#pragma unroll
    for (int i = 0; i < 4; i++) {
        float4 a = make_float4(0.f, 0.f, 0.f, 0.f);
#pragma unroll
        for (int s = 0; s < SPLITS; s++) {
            float4 t = ((const float4*)g_pacc)[((long)s * BT_ + row) * 4 + i];
            a.x += t.x; a.y += t.y; a.z += t.z; a.w += t.w;
        }
        o4[i] = make_float4(a.x * inv, a.y * inv, a.z * inv, a.w * inv);
    }
}

extern "C" void kernel_launch(void* const* d_in, const int* in_sizes, int n_in,
                              void* d_out, int out_size) {
    const float* x  = (const float*)d_in[0];
    const float* Wk = (const float*)d_in[1];
    const float* Wq = (const float*)d_in[2];
    const float* Wv = (const float*)d_in[3];
    float* out = (float*)d_out;

    proj_kernel<<<BT_ / 32, 128>>>(x, Wk, Wq, Wv);
    attn_kernel<<<dim3(T_ / 32, SPLITS, B_), 128>>>();
    combine_kernel<<<BT_ / 256, 256>>>(out);
}

// round 7
// speedup vs baseline: 2.0732x; 1.3783x over previous
#include <cuda_runtime.h>
#include <cstdint>

// Problem: B=4, T=4096, C=384 (n_embd), H=16 (head_size)
// out[b,t,:] = softmax_causal( (x@Wq)(x@Wk)^T / sqrt(H) ) @ (x@Wv)

#define B_     4
#define T_     4096
#define C_     384
#define H_     16
#define BT_    (B_ * T_)
#define SPLITS 8

__device__ float g_q[BT_ * H_];   // pre-scaled by H^-0.5 * log2(e)
__device__ float g_k[BT_ * H_];
__device__ float g_v[BT_ * H_];
__device__ float g_pacc[SPLITS * BT_ * H_];
__device__ float g_pl[SPLITS * BT_];

// ---------------- packed f32x2 helpers ----------------
__device__ __forceinline__ float ex2(float x) {
    float y; asm("ex2.approx.ftz.f32 %0, %1;" : "=f"(y) : "f"(x)); return y;
}
__device__ __forceinline__ double pk2(float lo, float hi) {
    double d; asm("mov.b64 %0, {%1, %2};" : "=d"(d) : "f"(lo), "f"(hi)); return d;
}
__device__ __forceinline__ void upk2(double d, float& lo, float& hi) {
    asm("mov.b64 {%0, %1}, %2;" : "=f"(lo), "=f"(hi) : "d"(d));
}
__device__ __forceinline__ double fma2(double a, double b, double c) {
    double d; asm("fma.rn.f32x2 %0, %1, %2, %3;" : "=d"(d) : "d"(a), "d"(b), "d"(c)); return d;
}
__device__ __forceinline__ double mul2(double a, double b) {
    double d; asm("mul.rn.f32x2 %0, %1, %2;" : "=d"(d) : "d"(a), "d"(b)); return d;
}
__device__ __forceinline__ double add2(double a, double b) {
    double d; asm("add.rn.f32x2 %0, %1, %2;" : "=d"(d) : "d"(a), "d"(b)); return d;
}
__device__ __forceinline__ void cp16(unsigned s, const void* g) {
    asm volatile("cp.async.cg.shared.global [%0], [%1], 16;" :: "r"(s), "l"(g));
}

// ---------------------------------------------------------------------------
// Kernel 1: fused QKV projection.
// Block = 256 threads = 32 rows x 8 C-segments (48 cols each). Grid = 512.
// x row stride 68 floats (272B): 16B-aligned for cp.async AND conflict-free
// LDS.128 (4r mod 32 spreads phases across bank quads). Chunks double-
// buffered via cp.async; partials merged through smem overlay.
// ---------------------------------------------------------------------------
#define PXS 68                      // x tile row stride in floats
#define PXB (32 * PXS * 4)          // 8704 B
#define PWB (3 * 64 * 16 * 4)       // 12288 B
#define PSTAGE (PXB + PWB)          // 20992 B

__global__ __launch_bounds__(256, 3)
void proj_kernel(const float* __restrict__ x,
                 const float* __restrict__ Wk,
                 const float* __restrict__ Wq,
                 const float* __restrict__ Wv) {
    // staging double buffered: 2*20992 = 41984 B; combine overlay: 43008 B
    __shared__ __align__(16) char sbuf[43008];

    const int tid = threadIdx.x;
    const int row = tid & 31;
    const int seg = tid >> 5;        // 0..7
    const long row0 = (long)blockIdx.x * 32;

    double aK[8], aQ[8], aV[8];
#pragma unroll
    for (int i = 0; i < 8; i++) { aK[i] = 0.0; aQ[i] = 0.0; aV[i] = 0.0; }

    const float4* xg = (const float4*)x;   // row stride = 96 float4
    const float4* wg[3] = { (const float4*)Wk, (const float4*)Wq, (const float4*)Wv };

    auto load_chunk = [&](int buf, int cc) {
        unsigned sxa = (unsigned)__cvta_generic_to_shared(sbuf + buf * PSTAGE);
        unsigned swa = sxa + PXB;
        // x tile 32x64: 512 float4; dst row stride 272B (16B-aligned)
        for (int i = tid; i < 512; i += 256) {
            int r = i >> 4, c4 = i & 15;
            cp16(sxa + (unsigned)(r * PXS + c4 * 4) * 4u,
                 xg + (row0 + r) * 96 + cc * 16 + c4);
        }
        // W chunks: 3 x 256 float4, contiguous
        for (int i = tid; i < 768; i += 256) {
            int m = i >> 8, j = i & 255;
            cp16(swa + (unsigned)(m * 256 + j) * 16u, wg[m] + cc * 256 + j);
        }
        asm volatile("cp.async.commit_group;");
    };

    load_chunk(0, 0);

    for (int cc = 0; cc < 6; cc++) {
        const int buf = cc & 1;
        if (cc < 5) {
            load_chunk(buf ^ 1, cc + 1);
            asm volatile("cp.async.wait_group 1;");
        } else {
            asm volatile("cp.async.wait_group 0;");
        }
        __syncthreads();

        const float* sx = (const float*)(sbuf + buf * PSTAGE);
        const float* sw = (const float*)(sbuf + buf * PSTAGE + PXB);

        // vectorized x read: this thread's 8 columns as 2 x LDS.128
        float xv8[8];
        {
            const float4* xr4 = (const float4*)&sx[row * PXS + seg * 8];
            float4 a = xr4[0], c = xr4[1];
            xv8[0]=a.x; xv8[1]=a.y; xv8[2]=a.z; xv8[3]=a.w;
            xv8[4]=c.x; xv8[5]=c.y; xv8[6]=c.z; xv8[7]=c.w;
        }
        const int cbase = seg * 8;
#pragma unroll
        for (int c = 0; c < 8; c++) {
            double xv2 = pk2(xv8[c], xv8[c]);
            const double2* wk2 = (const double2*)&sw[0 * 1024 + (cbase + c) * 16];
            const double2* wq2 = (const double2*)&sw[1 * 1024 + (cbase + c) * 16];
            const double2* wv2 = (const double2*)&sw[2 * 1024 + (cbase + c) * 16];
#pragma unroll
            for (int m = 0; m < 4; m++) {
                double2 k = wk2[m], q = wq2[m], v = wv2[m];
                aK[2*m+0] = fma2(xv2, k.x, aK[2*m+0]);
                aK[2*m+1] = fma2(xv2, k.y, aK[2*m+1]);
                aQ[2*m+0] = fma2(xv2, q.x, aQ[2*m+0]);
                aQ[2*m+1] = fma2(xv2, q.y, aQ[2*m+1]);
                aV[2*m+0] = fma2(xv2, v.x, aV[2*m+0]);
                aV[2*m+1] = fma2(xv2, v.y, aV[2*m+1]);
            }
        }
        __syncthreads();
    }

    // merge 8 segments: 1..7 publish, 0 accumulates + writes
    double* scomb = (double*)sbuf;   // [7][32][24]
    if (seg != 0) {
        double* d = &scomb[((seg - 1) * 32 + row) * 24];
#pragma unroll
        for (int i = 0; i < 8; i++) {
            d[i] = aK[i]; d[8 + i] = aQ[i]; d[16 + i] = aV[i];
        }
    }
    __syncthreads();
    if (seg == 0) {
        const float qscale = 0.25f * 1.4426950408889634f;  // H^-0.5 * log2(e)
        const double qs2 = pk2(qscale, qscale);
        const long r = row0 + row;
        double* qd = (double*)(g_q + r * 16);
        double* kd = (double*)(g_k + r * 16);
        double* vd = (double*)(g_v + r * 16);
#pragma unroll
        for (int i = 0; i < 8; i++) {
            double k = aK[i], q = aQ[i], v = aV[i];
#pragma unroll
            for (int s = 0; s < 7; s++) {
                const double* d = &scomb[(s * 32 + row) * 24];
                k = add2(k, d[i]); q = add2(q, d[8 + i]); v = add2(v, d[16 + i]);
            }
            kd[i] = k; qd[i] = mul2(q, qs2); vd[i] = v;
        }
    }
}

// ---------------------------------------------------------------------------
// Kernel 2: causal flash attention, split-K partials, Mq=2.
// Grid (128, 8, 4) = 4096 blocks. Block = 128 = 16 q-slots x 8 key-lanes;
// each thread owns 2 adjacent queries (k/v rows amortized over both).
// exp2-domain (no max) => split combining exact. cp.async double-buffered.
// ---------------------------------------------------------------------------
#define KT 64

__global__ __launch_bounds__(128, 4)
void attn_kernel() {
    __shared__ __align__(16) float4 sk4[2][4][KT];
    __shared__ __align__(16) float4 sv4[2][4][KT];

    const int tid = threadIdx.x;
    const int kj  = tid & 7;         // key lane (0..7)
    const int qs  = tid >> 3;        // q-slot (0..15)
    const int b   = blockIdx.z;
    const int split = blockIdx.y;
    const int tile  = (int)gridDim.x - 1 - (int)blockIdx.x;  // heavy-first
    const int q_start = tile * 32;
    const int gq0 = q_start + qs * 2;

    const int n_keys = q_start + 32;
    const int len = (n_keys + SPLITS - 1) / SPLITS;
    const int kb  = split * len;
    const int ke  = min(kb + len, n_keys);

    double acc[2][8];
#pragma unroll
    for (int m = 0; m < 2; m++)
#pragma unroll
        for (int i = 0; i < 8; i++) acc[m][i] = 0.0;
    float l[2] = {0.f, 0.f};

    if (kb < ke) {
        double q2[2][8];
#pragma unroll
        for (int m = 0; m < 2; m++) {
            const double2* qsrc = (const double2*)(g_q + ((long)b * T_ + gq0 + m) * 16);
#pragma unroll
            for (int i = 0; i < 4; i++) { double2 t = qsrc[i]; q2[m][2*i] = t.x; q2[m][2*i+1] = t.y; }
        }

        const float4* kg = (const float4*)(g_k + (long)b * T_ * 16);
        const float4* vg = (const float4*)(g_v + (long)b * T_ * 16);

        auto load_tile = [&](int buf, int t0, int nk) {
            for (int i = tid; i < nk * 4; i += 128) {
                int r = i >> 2, c = i & 3;
                cp16((unsigned)__cvta_generic_to_shared(&sk4[buf][c][r]), kg + (long)(t0 + r) * 4 + c);
                cp16((unsigned)__cvta_generic_to_shared(&sv4[buf][c][r]), vg + (long)(t0 + r) * 4 + c);
            }
            asm volatile("cp.async.commit_group;");
        };

        const bool safe = (ke <= q_start);
        const int nt = (ke - kb + KT - 1) / KT;
        load_tile(0, kb, min(KT, ke - kb));

        for (int t = 0; t < nt; t++) {
            const int t0 = kb + t * KT;
            const int nk = min(KT, ke - t0);
            if (t + 1 < nt) {
                load_tile((t + 1) & 1, t0 + KT, min(KT, ke - t0 - KT));
                asm volatile("cp.async.wait_group 1;");
            } else {
                asm volatile("cp.async.wait_group 0;");
            }
            __syncthreads();

            const int buf = t & 1;
#pragma unroll 2
            for (int j = kj; j < nk; j += 8) {
                float4 k0 = sk4[buf][0][j], k1 = sk4[buf][1][j];
                float4 k2 = sk4[buf][2][j], k3 = sk4[buf][3][j];
                double2 K0 = *(double2*)&k0, K1 = *(double2*)&k1;
                double2 K2 = *(double2*)&k2, K3 = *(double2*)&k3;
                float p[2];
#pragma unroll
                for (int m = 0; m < 2; m++) {
                    double sa = mul2(q2[m][0], K0.x);
                    sa = fma2(q2[m][2], K1.x, sa);
                    sa = fma2(q2[m][4], K2.x, sa);
                    sa = fma2(q2[m][6], K3.x, sa);
                    double sb = mul2(q2[m][1], K0.y);
                    sb = fma2(q2[m][3], K1.y, sb);
                    sb = fma2(q2[m][5], K2.y, sb);
                    sb = fma2(q2[m][7], K3.y, sb);
                    float lo, hi; upk2(add2(sa, sb), lo, hi);
                    float e = ex2(lo + hi);
                    p[m] = (safe || (t0 + j <= gq0 + m)) ? e : 0.f;
                    l[m] += p[m];
                }
                float4 v0 = sv4[buf][0][j], v1 = sv4[buf][1][j];
                float4 v2 = sv4[buf][2][j], v3 = sv4[buf][3][j];
                double2 V0 = *(double2*)&v0, V1 = *(double2*)&v1;
                double2 V2 = *(double2*)&v2, V3 = *(double2*)&v3;
#pragma unroll
                for (int m = 0; m < 2; m++) {
                    double p2 = pk2(p[m], p[m]);
                    acc[m][0] = fma2(p2, V0.x, acc[m][0]);
                    acc[m][1] = fma2(p2, V0.y, acc[m][1]);
                    acc[m][2] = fma2(p2, V1.x, acc[m][2]);
                    acc[m][3] = fma2(p2, V1.y, acc[m][3]);
                    acc[m][4] = fma2(p2, V2.x, acc[m][4]);
                    acc[m][5] = fma2(p2, V2.y, acc[m][5]);
                    acc[m][6] = fma2(p2, V3.x, acc[m][6]);
                    acc[m][7] = fma2(p2, V3.y, acc[m][7]);
                }
            }
            __syncthreads();
        }
    }

    // reduce across the 8 key-lanes of each q-slot
#pragma unroll
    for (int off = 1; off <= 4; off <<= 1) {
#pragma unroll
        for (int m = 0; m < 2; m++) {
            l[m] += __shfl_xor_sync(0xffffffffu, l[m], off);
#pragma unroll
            for (int i = 0; i < 8; i++)
                acc[m][i] = add2(acc[m][i], __shfl_xor_sync(0xffffffffu, acc[m][i], off));
        }
    }

    if (kj == 0) {
#pragma unroll
        for (int m = 0; m < 2; m++) {
            const long prow = (long)split * BT_ + (long)b * T_ + gq0 + m;
            g_pl[prow] = l[m];
            float o[16];
#pragma unroll
            for (int i = 0; i < 8; i++) upk2(acc[m][i], o[2*i], o[2*i+1]);
            float4* p4 = (float4*)(g_pacc + prow * 16);
#pragma unroll
            for (int i = 0; i < 4; i++)
                p4[i] = make_float4(o[4*i+0], o[4*i+1], o[4*i+2], o[4*i+3]);
        }
    }
}

// ---------------------------------------------------------------------------
// Kernel 3: combine split partials. One thread per output row.
// ---------------------------------------------------------------------------
__global__ __launch_bounds__(256)
void combine_kernel(float* __restrict__ out) {
    const int row = blockIdx.x * 256 + threadIdx.x;
    float l = 0.f;
#pragma unroll
    for (int s = 0; s < SPLITS; s++) l += g_pl[(long)s * BT_ + row];
    const float inv = 1.0f / l;

    float4* o4 = (float4*)out + (long)row * 4;
#pragma unroll
    for (int i = 0; i < 4; i++) {
        float4 a = make_float4(0.f, 0.f, 0.f, 0.f);
#pragma unroll
        for (int s = 0; s < SPLITS; s++) {
            float4 t = ((const float4*)g_pacc)[((long)s * BT_ + row) * 4 + i];
            a.x += t.x; a.y += t.y; a.z += t.z; a.w += t.w;
        }
        o4[i] = make_float4(a.x * inv, a.y * inv, a.z * inv, a.w * inv);
    }
}

extern "C" void kernel_launch(void* const* d_in, const int* in_sizes, int n_in,
                              void* d_out, int out_size) {
    const float* x  = (const float*)d_in[0];
    const float* Wk = (const float*)d_in[1];
    const float* Wq = (const float*)d_in[2];
    const float* Wv = (const float*)d_in[3];
    float* out = (float*)d_out;

    proj_kernel<<<BT_ / 32, 256>>>(x, Wk, Wq, Wv);
    attn_kernel<<<dim3(T_ / 32, SPLITS, B_), 128>>>();
    combine_kernel<<<BT_ / 256, 256>>>(out);
}